// round 15
// baseline (speedup 1.0000x reference)
#include <cuda_runtime.h>
#include <cuda_fp16.h>
#include <cuda_bf16.h>
#include <mma.h>
#include <math.h>

using namespace nvcuda;

#define Nn 8192
#define Dd 64
#define NCHUNK 256             // row chunks in v-pass
#define VROWS (Nn / NCHUNK)    // 32 rows per chunk
#define VCOLS 2048             // cols per tile (128 threads * 16)
#define NTILE (Nn / VCOLS)     // 4

#define LOG_AB (-9.010913347f)   // -ln(8192)
#define LOG2E  (1.4426950408889634f)
#define LN2    (0.6931471805599453f)
#define BIAS   (12.0f)

#define LDAB 72                  // padded bf16 row stride (multiple of 8, breaks conflicts)
#define LDC  68                  // padded fp32 row stride (multiple of 4)

// ---------------- device scratch ----------
__device__ unsigned char d_Q[(size_t)Nn * Nn];   // quantized cost, 67 MB
__device__ __nv_bfloat16 d_XPb[(size_t)Nn * Dd];
__device__ __nv_bfloat16 d_XQb[(size_t)Nn * Dd];
__device__ float d_x2[Nn], d_y2[Nn];
__device__ float d_u[Nn], d_v[Nn];
__device__ float d_spart[NCHUNK][Nn];
__device__ float d_Tpart[NCHUNK][Nn];
__device__ float d_rj[Nn];
__device__ unsigned int d_cmax_bits;
__device__ unsigned int d_mx2_bits = 0u;   // max row norm XP (idempotent across replays)
__device__ unsigned int d_my2_bits = 0u;   // max row norm XQ
__device__ float d_invAlpha;               // 1/alpha2
__device__ float d_qafr;                   // quant LSB in log2 units (positive)
__device__ float d_c0f;                    // BIAS + 1024*qafr
__device__ float d_csf;                    // c0f - 128

__device__ __forceinline__ __half2 h2exp2_fast(__half2 x) {
    unsigned xi = *reinterpret_cast<unsigned*>(&x);
    unsigned ri;
    asm("ex2.approx.f16x2 %0, %1;" : "=r"(ri) : "r"(xi));
    return *reinterpret_cast<__half2*>(&ri);
}
__device__ __forceinline__ __half2 u32_as_h2(unsigned x) {
    return *reinterpret_cast<__half2*>(&x);
}
__device__ __forceinline__ float ub_from(float mx2, float my2) {
    float s = sqrtf(mx2) + sqrtf(my2);
    return s * s;
}

// ---------------- prep: bf16 convert + row norms + u/v init + norm maxes ---
__global__ void prep_kernel(const float* __restrict__ XP,
                            const float* __restrict__ XQ) {
    int gwarp = (blockIdx.x * blockDim.x + threadIdx.x) >> 5;
    int lane = threadIdx.x & 31;
    const float* src;
    __nv_bfloat16* bdst;
    float* ndst;
    int row;
    bool isP = gwarp < Nn;
    if (isP) { src = XP; bdst = d_XPb; ndst = d_x2; row = gwarp; }
    else     { src = XQ; bdst = d_XQb; ndst = d_y2; row = gwarp - Nn; }
    const float* r = src + (size_t)row * Dd;
    float a = r[lane];
    float b = r[lane + 32];
    bdst[(size_t)row * Dd + lane]      = __float2bfloat16(a);
    bdst[(size_t)row * Dd + lane + 32] = __float2bfloat16(b);
    float s = a * a + b * b;
    #pragma unroll
    for (int o = 16; o; o >>= 1) s += __shfl_xor_sync(0xffffffffu, s, o);
    if (lane == 0) {
        ndst[row] = s;
        atomicMax(isP ? &d_mx2_bits : &d_my2_bits, __float_as_uint(s));
        if (isP) { d_u[row] = 0.0f; d_v[row] = 0.0f; }
        if (gwarp == 0) d_cmax_bits = 0u;
    }
}

// ---------------- single wmma bf16 GEMM: quantize-store (UB scale) + exact max
__global__ void wmma_gemm_kernel() {
    __shared__ __align__(16) unsigned char buf[128 * LDC * 4];  // unioned
    __nv_bfloat16* Asm = (__nv_bfloat16*)buf;                   // [128][LDAB]
    __nv_bfloat16* Bsm = (__nv_bfloat16*)(buf + 128 * LDAB * 2);// [64][LDAB]
    float* Csm = (float*)buf;                                   // [128][LDC] (reused)
    __shared__ float y2s[64];
    __shared__ float red[8];

    int tid = threadIdx.x;             // 256
    int m0 = blockIdx.y * 128;
    int n0 = blockIdx.x * 64;

    // qs from norm UB (same formula as scale_kernel -> consistent)
    float qs = 255.0f / ub_from(__uint_as_float(d_mx2_bits),
                                __uint_as_float(d_my2_bits));

    {
        const uint4* gA = (const uint4*)(d_XPb + (size_t)m0 * Dd);
        uint4* sA = (uint4*)Asm;                      // row stride LDAB/8 = 9 uint4
        #pragma unroll
        for (int p = 0; p < 4; ++p) {
            int f = p * 256 + tid;                    // 0..1023
            int row = f >> 3, c = f & 7;
            sA[row * (LDAB / 8) + c] = gA[f];
        }
        const uint4* gB = (const uint4*)(d_XQb + (size_t)n0 * Dd);
        uint4* sB = (uint4*)Bsm;
        #pragma unroll
        for (int p = 0; p < 2; ++p) {
            int f = p * 256 + tid;                    // 0..511
            int row = f >> 3, c = f & 7;
            sB[row * (LDAB / 8) + c] = gB[f];
        }
        if (tid < 64) y2s[tid] = d_y2[n0 + tid];
    }
    __syncthreads();

    int w = tid >> 5;
    int wm = (w & 3) * 32, wn = (w >> 2) * 32;
    wmma::fragment<wmma::accumulator, 16, 16, 16, float> acc[2][2];
    #pragma unroll
    for (int i = 0; i < 2; ++i)
        #pragma unroll
        for (int j = 0; j < 2; ++j)
            wmma::fill_fragment(acc[i][j], 0.0f);

    #pragma unroll
    for (int k0 = 0; k0 < Dd; k0 += 16) {
        wmma::fragment<wmma::matrix_a, 16, 16, 16, __nv_bfloat16, wmma::row_major> af[2];
        wmma::fragment<wmma::matrix_b, 16, 16, 16, __nv_bfloat16, wmma::col_major> bf[2];
        #pragma unroll
        for (int i = 0; i < 2; ++i)
            wmma::load_matrix_sync(af[i], Asm + (wm + 16 * i) * LDAB + k0, LDAB);
        #pragma unroll
        for (int j = 0; j < 2; ++j)
            wmma::load_matrix_sync(bf[j], Bsm + (wn + 16 * j) * LDAB + k0, LDAB);
        #pragma unroll
        for (int i = 0; i < 2; ++i)
            #pragma unroll
            for (int j = 0; j < 2; ++j)
                wmma::mma_sync(acc[i][j], af[i], bf[j], acc[i][j]);
    }
    __syncthreads();   // done reading Asm/Bsm; Csm may overwrite
    #pragma unroll
    for (int i = 0; i < 2; ++i)
        #pragma unroll
        for (int j = 0; j < 2; ++j)
            wmma::store_matrix_sync(Csm + (wm + 16 * i) * LDC + (wn + 16 * j),
                                    acc[i][j], LDC, wmma::mem_row_major);
    __syncthreads();

    // epilogue: thread handles row r = tid>>1, 32 cols; quantize + exact max
    int r = tid >> 1, ch = (tid & 1) * 32;
    int m = m0 + r;
    float xm = d_x2[m];

    float cmaxl = 0.0f;
    unsigned wq[8];
    #pragma unroll
    for (int g = 0; g < 8; ++g) {
        unsigned bts = 0;
        #pragma unroll
        for (int e = 0; e < 4; ++e) {
            int j = g * 4 + e;
            float dot = Csm[r * LDC + ch + j];
            float c = fmaxf(xm + y2s[ch + j] - 2.0f * dot, 0.0f);
            cmaxl = fmaxf(cmaxl, c);
            unsigned q = __float2uint_rn(fminf(c * qs, 255.0f));
            bts |= q << (8 * e);
        }
        wq[g] = bts;
    }
    uint4* dst = (uint4*)(d_Q + (size_t)m * Nn + n0 + ch);
    dst[0] = make_uint4(wq[0], wq[1], wq[2], wq[3]);
    dst[1] = make_uint4(wq[4], wq[5], wq[6], wq[7]);

    #pragma unroll
    for (int o = 16; o; o >>= 1)
        cmaxl = fmaxf(cmaxl, __shfl_xor_sync(0xffffffffu, cmaxl, o));
    if ((tid & 31) == 0) red[tid >> 5] = cmaxl;
    __syncthreads();
    if (tid == 0) {
        float bm = red[0];
        #pragma unroll
        for (int q = 1; q < 8; ++q) bm = fmaxf(bm, red[q]);
        atomicMax(&d_cmax_bits, __float_as_uint(bm)); // nonneg: bit order == value order
    }
}

// runtime constants from exact Cmax + UB
__global__ void scale_kernel() {
    float cmax = __uint_as_float(d_cmax_bits);
    float ub = ub_from(__uint_as_float(d_mx2_bits), __uint_as_float(d_my2_bits));
    float negS = -1.0f / (0.05f * cmax);
    float alpha2 = negS * LOG2E;               // negative
    float qafr = -alpha2 * ub * (1.0f / 255.0f);   // positive LSB in log2 units
    d_invAlpha = 1.0f / alpha2;
    d_qafr = qafr;
    d_c0f = BIAS + 1024.0f * qafr;
    d_csf = BIAS + 1024.0f * qafr - 128.0f;
}

// ---------------- u-pass: u_new = up - rc*ln2 - ln( sum_j 2^(a' + v_j*log2e) )
__global__ void upass_kernel() {
    __shared__ __half2 vs2[Nn / 2];    // vc_j = v_j*LOG2E + csf, packed pairs
    int tid = threadIdx.x;             // 256
    float csf = d_csf;
    float qafr = d_qafr;
    #pragma unroll
    for (int p = 0; p < 8; ++p) {
        int idx = p * 256 + tid;       // float4 index
        float4 f = *(const float4*)&d_v[idx * 4];
        vs2[idx * 2]     = __floats2half2_rn(fmaf(f.x, LOG2E, csf), fmaf(f.y, LOG2E, csf));
        vs2[idx * 2 + 1] = __floats2half2_rn(fmaf(f.z, LOG2E, csf), fmaf(f.w, LOG2E, csf));
    }
    __syncthreads();

    int warp = tid >> 5, lane = tid & 31;
    int row = blockIdx.x * 8 + warp;
    float up = d_u[row];
    const unsigned char* Qrow = d_Q + (size_t)row * Nn;
    const __half2 qa2 = __float2half2_rn(-qafr);
    const __half2 c128 = __float2half2_rn(128.0f);

    float2 fs[8] = {};
    #pragma unroll
    for (int blk = 0; blk < 2; ++blk) {
        unsigned hacc[8] = {};         // half2 accumulators as u32
        #pragma unroll
        for (int it = 0; it < 8; ++it) {
            int j = (blk * 8 + it) * 512 + lane * 16;
            uint4 raw = *(const uint4*)(Qrow + j);
            uint4 v01 = *(const uint4*)&vs2[j >> 1];
            uint4 v23 = *(const uint4*)&vs2[(j >> 1) + 4];
            unsigned w[4] = {raw.x, raw.y, raw.z, raw.w};
            __half2 vcp[8];
            vcp[0] = u32_as_h2(v01.x); vcp[1] = u32_as_h2(v01.y);
            vcp[2] = u32_as_h2(v01.z); vcp[3] = u32_as_h2(v01.w);
            vcp[4] = u32_as_h2(v23.x); vcp[5] = u32_as_h2(v23.y);
            vcp[6] = u32_as_h2(v23.z); vcp[7] = u32_as_h2(v23.w);
            #pragma unroll
            for (int k = 0; k < 4; ++k) {
                __half2 hA = u32_as_h2(__byte_perm(w[k], 0x64646464u, 0x4140));
                __half2 hB = u32_as_h2(__byte_perm(w[k], 0x64646464u, 0x4342));
                __half2 aA = __hadd2(__hfma2(hA, qa2, c128), vcp[2 * k]);
                __half2 aB = __hadd2(__hfma2(hB, qa2, c128), vcp[2 * k + 1]);
                __half2 sA = __hadd2(u32_as_h2(hacc[2 * k]), h2exp2_fast(aA));
                __half2 sB = __hadd2(u32_as_h2(hacc[2 * k + 1]), h2exp2_fast(aB));
                hacc[2 * k] = *reinterpret_cast<unsigned*>(&sA);
                hacc[2 * k + 1] = *reinterpret_cast<unsigned*>(&sB);
            }
        }
        #pragma unroll
        for (int q = 0; q < 8; ++q) {
            float2 g = __half22float2(u32_as_h2(hacc[q]));
            fs[q].x += g.x; fs[q].y += g.y;
        }
    }
    float s = 0.f;
    #pragma unroll
    for (int q = 0; q < 8; ++q) s += fs[q].x + fs[q].y;
    #pragma unroll
    for (int o = 16; o; o >>= 1) s += __shfl_xor_sync(0xffffffffu, s, o);
    if (lane == 0) {
        float rc = (up - LOG_AB) * LOG2E - BIAS;
        d_u[row] = up - rc * LN2 - __logf(s);
    }
}

// ---------------- v-pass: partial col sums of 2^(a' + u_i*log2e) -----------
template <bool FINAL>
__global__ void vpass_kernel() {
    __shared__ __half2 us2[VROWS];     // uc_i = u_i*LOG2E + csf, duplicated halves
    int tid = threadIdx.x;             // 128
    int tile = blockIdx.x;             // 0..NTILE-1
    int chunk = blockIdx.y;            // 0..NCHUNK-1
    int i0 = chunk * VROWS;
    float csf = d_csf;
    float qafr = d_qafr;
    float c0f = d_c0f;
    if (tid < VROWS)
        us2[tid] = __float2half2_rn(fmaf(d_u[i0 + tid], LOG2E, csf));
    __syncthreads();

    int j = tile * VCOLS + tid * 16;
    const unsigned char* Qp = d_Q + (size_t)i0 * Nn + j;
    const __half2 qa2 = __float2half2_rn(-qafr);
    const __half2 c128 = __float2half2_rn(128.0f);

    float2 fs[8] = {};
    float2 ts[8] = {};

    #pragma unroll
    for (int blk = 0; blk < VROWS / 8; ++blk) {
        unsigned hacc[8] = {};
        #pragma unroll
        for (int it = 0; it < 8; ++it) {
            int i = blk * 8 + it;
            __half2 uc = us2[i];
            uint4 raw = *(const uint4*)(Qp + (size_t)i * Nn);
            unsigned w[4] = {raw.x, raw.y, raw.z, raw.w};
            #pragma unroll
            for (int k = 0; k < 4; ++k) {
                __half2 hA = u32_as_h2(__byte_perm(w[k], 0x64646464u, 0x4140));
                __half2 hB = u32_as_h2(__byte_perm(w[k], 0x64646464u, 0x4342));
                __half2 aA = __hadd2(__hfma2(hA, qa2, c128), uc);
                __half2 aB = __hadd2(__hfma2(hB, qa2, c128), uc);
                __half2 eA = h2exp2_fast(aA);
                __half2 eB = h2exp2_fast(aB);
                __half2 sA = __hadd2(u32_as_h2(hacc[2 * k]), eA);
                __half2 sB = __hadd2(u32_as_h2(hacc[2 * k + 1]), eB);
                hacc[2 * k] = *reinterpret_cast<unsigned*>(&sA);
                hacc[2 * k + 1] = *reinterpret_cast<unsigned*>(&sB);
                if (FINAL) {
                    // a' = hf*(-qafr) + c0f  (log2-domain incl BIAS)
                    float2 hfA = __half22float2(hA);
                    float2 hfB = __half22float2(hB);
                    float2 efA = __half22float2(eA);
                    float2 efB = __half22float2(eB);
                    float apAx = fmaf(hfA.x, -qafr, c0f);
                    float apAy = fmaf(hfA.y, -qafr, c0f);
                    float apBx = fmaf(hfB.x, -qafr, c0f);
                    float apBy = fmaf(hfB.y, -qafr, c0f);
                    ts[2 * k].x = fmaf(apAx, efA.x, ts[2 * k].x);
                    ts[2 * k].y = fmaf(apAy, efA.y, ts[2 * k].y);
                    ts[2 * k + 1].x = fmaf(apBx, efB.x, ts[2 * k + 1].x);
                    ts[2 * k + 1].y = fmaf(apBy, efB.y, ts[2 * k + 1].y);
                }
            }
        }
        #pragma unroll
        for (int q = 0; q < 8; ++q) {
            float2 g = __half22float2(u32_as_h2(hacc[q]));
            fs[q].x += g.x; fs[q].y += g.y;
        }
    }
    #pragma unroll
    for (int q = 0; q < 4; ++q)
        *(float4*)&d_spart[chunk][j + q * 4] =
            make_float4(fs[2 * q].x, fs[2 * q].y, fs[2 * q + 1].x, fs[2 * q + 1].y);
    if (FINAL) {
        #pragma unroll
        for (int q = 0; q < 4; ++q)
            *(float4*)&d_Tpart[chunk][j + q * 4] =
                make_float4(ts[2 * q].x, ts[2 * q].y, ts[2 * q + 1].x, ts[2 * q + 1].y);
    }
}

// deterministic fixed-order merge of v partials
__global__ void vfinalize_kernel() {
    int j = blockIdx.x * blockDim.x + threadIdx.x;
    float s = 0.f;
    #pragma unroll 32
    for (int c = 0; c < NCHUNK; ++c) s += d_spart[c][j];
    float vp = d_v[j];
    float cc = (vp - LOG_AB) * LOG2E - BIAS;
    d_v[j] = vp - cc * LN2 - __logf(s);
}

// r_j = T_j/s_j in C units: ((sum a'e / sum e) - 12) / alpha2
__global__ void rj_kernel() {
    int j = blockIdx.x * blockDim.x + threadIdx.x;
    float s = 0.f, t = 0.f;
    #pragma unroll 32
    for (int c = 0; c < NCHUNK; ++c) { s += d_spart[c][j]; t += d_Tpart[c][j]; }
    d_rj[j] = (t / s - BIAS) * d_invAlpha;
}

__global__ void result_kernel(float* __restrict__ out) {
    __shared__ float red[256];
    int tid = threadIdx.x;
    float s = 0.f;
    for (int j = tid; j < Nn; j += 256) s += d_rj[j];
    red[tid] = s;
    __syncthreads();
    for (int o = 128; o; o >>= 1) {
        if (tid < o) red[tid] += red[tid + o];
        __syncthreads();
    }
    if (tid == 0) out[0] = red[0] * (1.0f / Nn);
}

// ---------------------------------------------------------------------------
extern "C" void kernel_launch(void* const* d_in, const int* in_sizes, int n_in,
                              void* d_out, int out_size) {
    const float* XP = (const float*)d_in[0];
    const float* XQ = (const float*)d_in[1];
    float* out = (float*)d_out;

    prep_kernel<<<(2 * Nn) / 8, 256>>>(XP, XQ);
    wmma_gemm_kernel<<<dim3(Nn / 64, Nn / 128), 256>>>();
    scale_kernel<<<1, 1>>>();

    for (int t = 0; t < 20; ++t) {
        upass_kernel<<<Nn / 8, 256>>>();
        if (t < 19) {
            vpass_kernel<false><<<dim3(NTILE, NCHUNK), 128>>>();
            vfinalize_kernel<<<Nn / 256, 256>>>();
        } else {
            vpass_kernel<true><<<dim3(NTILE, NCHUNK), 128>>>();
            rj_kernel<<<Nn / 256, 256>>>();
            result_kernel<<<1, 256>>>(out);
        }
    }
}

// round 16
// speedup vs baseline: 1.6505x; 1.6505x over previous
#include <cuda_runtime.h>
#include <cuda_fp16.h>
#include <cuda_bf16.h>
#include <mma.h>
#include <math.h>

using namespace nvcuda;

#define Nn 8192
#define Dd 64
#define NCHUNK 128             // row chunks in v-pass (proven config)
#define VROWS (Nn / NCHUNK)    // 64 rows per chunk
#define VCOLS 2048             // cols per tile (128 threads * 16)
#define NTILE (Nn / VCOLS)     // 4

#define LOG_AB (-9.010913347f)   // -ln(8192)
#define LOG2E  (1.4426950408889634f)
#define LN2    (0.6931471805599453f)
#define BIAS   (12.0f)

#define LDAB 72                  // padded bf16 row stride (multiple of 8, breaks conflicts)
#define LDC  68                  // padded fp32 row stride (multiple of 4)

// ---------------- device scratch ----------
__device__ unsigned char d_Q[(size_t)Nn * Nn];   // quantized cost, 67 MB
__device__ __nv_bfloat16 d_XPb[(size_t)Nn * Dd];
__device__ __nv_bfloat16 d_XQb[(size_t)Nn * Dd];
__device__ float d_x2[Nn], d_y2[Nn];
__device__ float d_u[Nn], d_v[Nn];
__device__ float d_spart[NCHUNK][Nn];
__device__ float d_Tpart[NCHUNK][Nn];
__device__ float d_rj[Nn];
__device__ unsigned int d_cmax_bits;
__device__ unsigned int d_mx2_bits = 0u;   // max row norm XP (idempotent across replays)
__device__ unsigned int d_my2_bits = 0u;   // max row norm XQ
__device__ float d_invAlpha;               // 1/alpha2
__device__ float d_qafr;                   // quant LSB in log2 units (positive)
__device__ float d_c0f;                    // BIAS + 1024*qafr
__device__ float d_csf;                    // c0f - 128

__device__ __forceinline__ __half2 h2exp2_fast(__half2 x) {
    unsigned xi = *reinterpret_cast<unsigned*>(&x);
    unsigned ri;
    asm("ex2.approx.f16x2 %0, %1;" : "=r"(ri) : "r"(xi));
    return *reinterpret_cast<__half2*>(&ri);
}
__device__ __forceinline__ __half2 u32_as_h2(unsigned x) {
    return *reinterpret_cast<__half2*>(&x);
}
__device__ __forceinline__ float ub_from(float mx2, float my2) {
    float s = sqrtf(mx2) + sqrtf(my2);
    return s * s;
}

// ---------------- prep: bf16 convert + row norms + u/v init + norm maxes ---
__global__ void prep_kernel(const float* __restrict__ XP,
                            const float* __restrict__ XQ) {
    int gwarp = (blockIdx.x * blockDim.x + threadIdx.x) >> 5;
    int lane = threadIdx.x & 31;
    const float* src;
    __nv_bfloat16* bdst;
    float* ndst;
    int row;
    bool isP = gwarp < Nn;
    if (isP) { src = XP; bdst = d_XPb; ndst = d_x2; row = gwarp; }
    else     { src = XQ; bdst = d_XQb; ndst = d_y2; row = gwarp - Nn; }
    const float* r = src + (size_t)row * Dd;
    float a = r[lane];
    float b = r[lane + 32];
    bdst[(size_t)row * Dd + lane]      = __float2bfloat16(a);
    bdst[(size_t)row * Dd + lane + 32] = __float2bfloat16(b);
    float s = a * a + b * b;
    #pragma unroll
    for (int o = 16; o; o >>= 1) s += __shfl_xor_sync(0xffffffffu, s, o);
    if (lane == 0) {
        ndst[row] = s;
        atomicMax(isP ? &d_mx2_bits : &d_my2_bits, __float_as_uint(s));
        if (isP) { d_u[row] = 0.0f; d_v[row] = 0.0f; }
        if (gwarp == 0) d_cmax_bits = 0u;
    }
}

// ---------------- single wmma bf16 GEMM: quantize-store (UB scale) + exact max
__global__ void wmma_gemm_kernel() {
    __shared__ __align__(16) unsigned char buf[128 * LDC * 4];  // unioned
    __nv_bfloat16* Asm = (__nv_bfloat16*)buf;                   // [128][LDAB]
    __nv_bfloat16* Bsm = (__nv_bfloat16*)(buf + 128 * LDAB * 2);// [64][LDAB]
    float* Csm = (float*)buf;                                   // [128][LDC] (reused)
    __shared__ float y2s[64];
    __shared__ float red[8];

    int tid = threadIdx.x;             // 256
    int m0 = blockIdx.y * 128;
    int n0 = blockIdx.x * 64;

    // qs from norm UB (same formula as scale_kernel -> consistent)
    float qs = 255.0f / ub_from(__uint_as_float(d_mx2_bits),
                                __uint_as_float(d_my2_bits));

    {
        const uint4* gA = (const uint4*)(d_XPb + (size_t)m0 * Dd);
        uint4* sA = (uint4*)Asm;                      // row stride LDAB/8 = 9 uint4
        #pragma unroll
        for (int p = 0; p < 4; ++p) {
            int f = p * 256 + tid;                    // 0..1023
            int row = f >> 3, c = f & 7;
            sA[row * (LDAB / 8) + c] = gA[f];
        }
        const uint4* gB = (const uint4*)(d_XQb + (size_t)n0 * Dd);
        uint4* sB = (uint4*)Bsm;
        #pragma unroll
        for (int p = 0; p < 2; ++p) {
            int f = p * 256 + tid;                    // 0..511
            int row = f >> 3, c = f & 7;
            sB[row * (LDAB / 8) + c] = gB[f];
        }
        if (tid < 64) y2s[tid] = d_y2[n0 + tid];
    }
    __syncthreads();

    int w = tid >> 5;
    int wm = (w & 3) * 32, wn = (w >> 2) * 32;
    wmma::fragment<wmma::accumulator, 16, 16, 16, float> acc[2][2];
    #pragma unroll
    for (int i = 0; i < 2; ++i)
        #pragma unroll
        for (int j = 0; j < 2; ++j)
            wmma::fill_fragment(acc[i][j], 0.0f);

    #pragma unroll
    for (int k0 = 0; k0 < Dd; k0 += 16) {
        wmma::fragment<wmma::matrix_a, 16, 16, 16, __nv_bfloat16, wmma::row_major> af[2];
        wmma::fragment<wmma::matrix_b, 16, 16, 16, __nv_bfloat16, wmma::col_major> bf[2];
        #pragma unroll
        for (int i = 0; i < 2; ++i)
            wmma::load_matrix_sync(af[i], Asm + (wm + 16 * i) * LDAB + k0, LDAB);
        #pragma unroll
        for (int j = 0; j < 2; ++j)
            wmma::load_matrix_sync(bf[j], Bsm + (wn + 16 * j) * LDAB + k0, LDAB);
        #pragma unroll
        for (int i = 0; i < 2; ++i)
            #pragma unroll
            for (int j = 0; j < 2; ++j)
                wmma::mma_sync(acc[i][j], af[i], bf[j], acc[i][j]);
    }
    __syncthreads();   // done reading Asm/Bsm; Csm may overwrite
    #pragma unroll
    for (int i = 0; i < 2; ++i)
        #pragma unroll
        for (int j = 0; j < 2; ++j)
            wmma::store_matrix_sync(Csm + (wm + 16 * i) * LDC + (wn + 16 * j),
                                    acc[i][j], LDC, wmma::mem_row_major);
    __syncthreads();

    // epilogue: thread handles row r = tid>>1, 32 cols; quantize + exact max
    int r = tid >> 1, ch = (tid & 1) * 32;
    int m = m0 + r;
    float xm = d_x2[m];

    float cmaxl = 0.0f;
    unsigned wq[8];
    #pragma unroll
    for (int g = 0; g < 8; ++g) {
        unsigned bts = 0;
        #pragma unroll
        for (int e = 0; e < 4; ++e) {
            int j = g * 4 + e;
            float dot = Csm[r * LDC + ch + j];
            float c = fmaxf(xm + y2s[ch + j] - 2.0f * dot, 0.0f);
            cmaxl = fmaxf(cmaxl, c);
            unsigned q = __float2uint_rn(fminf(c * qs, 255.0f));
            bts |= q << (8 * e);
        }
        wq[g] = bts;
    }
    uint4* dst = (uint4*)(d_Q + (size_t)m * Nn + n0 + ch);
    dst[0] = make_uint4(wq[0], wq[1], wq[2], wq[3]);
    dst[1] = make_uint4(wq[4], wq[5], wq[6], wq[7]);

    #pragma unroll
    for (int o = 16; o; o >>= 1)
        cmaxl = fmaxf(cmaxl, __shfl_xor_sync(0xffffffffu, cmaxl, o));
    if ((tid & 31) == 0) red[tid >> 5] = cmaxl;
    __syncthreads();
    if (tid == 0) {
        float bm = red[0];
        #pragma unroll
        for (int q = 1; q < 8; ++q) bm = fmaxf(bm, red[q]);
        atomicMax(&d_cmax_bits, __float_as_uint(bm)); // nonneg: bit order == value order
    }
}

// runtime constants from exact Cmax + UB
__global__ void scale_kernel() {
    float cmax = __uint_as_float(d_cmax_bits);
    float ub = ub_from(__uint_as_float(d_mx2_bits), __uint_as_float(d_my2_bits));
    float negS = -1.0f / (0.05f * cmax);
    float alpha2 = negS * LOG2E;               // negative
    float qafr = -alpha2 * ub * (1.0f / 255.0f);   // positive LSB in log2 units
    d_invAlpha = 1.0f / alpha2;
    d_qafr = qafr;
    d_c0f = BIAS + 1024.0f * qafr;
    d_csf = BIAS + 1024.0f * qafr - 128.0f;
}

// ---------------- u-pass: u_new = up - rc*ln2 - ln( sum_j 2^(a' + v_j*log2e) )
__global__ void upass_kernel() {
    __shared__ __half2 vs2[Nn / 2];    // vc_j = v_j*LOG2E + csf, packed pairs
    int tid = threadIdx.x;             // 256
    float csf = d_csf;
    float qafr = d_qafr;
    #pragma unroll
    for (int p = 0; p < 8; ++p) {
        int idx = p * 256 + tid;       // float4 index
        float4 f = *(const float4*)&d_v[idx * 4];
        vs2[idx * 2]     = __floats2half2_rn(fmaf(f.x, LOG2E, csf), fmaf(f.y, LOG2E, csf));
        vs2[idx * 2 + 1] = __floats2half2_rn(fmaf(f.z, LOG2E, csf), fmaf(f.w, LOG2E, csf));
    }
    __syncthreads();

    int warp = tid >> 5, lane = tid & 31;
    int row = blockIdx.x * 8 + warp;
    float up = d_u[row];
    const unsigned char* Qrow = d_Q + (size_t)row * Nn;
    const __half2 qa2 = __float2half2_rn(-qafr);
    const __half2 c128 = __float2half2_rn(128.0f);

    float2 fs[8] = {};
    #pragma unroll
    for (int blk = 0; blk < 2; ++blk) {
        unsigned hacc[8] = {};         // half2 accumulators as u32
        #pragma unroll
        for (int it = 0; it < 8; ++it) {
            int j = (blk * 8 + it) * 512 + lane * 16;
            uint4 raw = *(const uint4*)(Qrow + j);
            uint4 v01 = *(const uint4*)&vs2[j >> 1];
            uint4 v23 = *(const uint4*)&vs2[(j >> 1) + 4];
            unsigned w[4] = {raw.x, raw.y, raw.z, raw.w};
            __half2 vcp[8];
            vcp[0] = u32_as_h2(v01.x); vcp[1] = u32_as_h2(v01.y);
            vcp[2] = u32_as_h2(v01.z); vcp[3] = u32_as_h2(v01.w);
            vcp[4] = u32_as_h2(v23.x); vcp[5] = u32_as_h2(v23.y);
            vcp[6] = u32_as_h2(v23.z); vcp[7] = u32_as_h2(v23.w);
            #pragma unroll
            for (int k = 0; k < 4; ++k) {
                __half2 hA = u32_as_h2(__byte_perm(w[k], 0x64646464u, 0x4140));
                __half2 hB = u32_as_h2(__byte_perm(w[k], 0x64646464u, 0x4342));
                __half2 aA = __hadd2(__hfma2(hA, qa2, c128), vcp[2 * k]);
                __half2 aB = __hadd2(__hfma2(hB, qa2, c128), vcp[2 * k + 1]);
                __half2 sA = __hadd2(u32_as_h2(hacc[2 * k]), h2exp2_fast(aA));
                __half2 sB = __hadd2(u32_as_h2(hacc[2 * k + 1]), h2exp2_fast(aB));
                hacc[2 * k] = *reinterpret_cast<unsigned*>(&sA);
                hacc[2 * k + 1] = *reinterpret_cast<unsigned*>(&sB);
            }
        }
        #pragma unroll
        for (int q = 0; q < 8; ++q) {
            float2 g = __half22float2(u32_as_h2(hacc[q]));
            fs[q].x += g.x; fs[q].y += g.y;
        }
    }
    float s = 0.f;
    #pragma unroll
    for (int q = 0; q < 8; ++q) s += fs[q].x + fs[q].y;
    #pragma unroll
    for (int o = 16; o; o >>= 1) s += __shfl_xor_sync(0xffffffffu, s, o);
    if (lane == 0) {
        float rc = (up - LOG_AB) * LOG2E - BIAS;
        d_u[row] = up - rc * LN2 - __logf(s);
    }
}

// ---------------- v-pass: partial col sums of 2^(a' + u_i*log2e) -----------
template <bool FINAL>
__global__ void vpass_kernel() {
    __shared__ __half2 us2[VROWS];     // uc_i = u_i*LOG2E + csf, duplicated halves
    int tid = threadIdx.x;             // 128
    int tile = blockIdx.x;             // 0..NTILE-1
    int chunk = blockIdx.y;            // 0..NCHUNK-1
    int i0 = chunk * VROWS;
    float csf = d_csf;
    float qafr = d_qafr;
    float c0f = d_c0f;
    if (tid < VROWS)
        us2[tid] = __float2half2_rn(fmaf(d_u[i0 + tid], LOG2E, csf));
    __syncthreads();

    int j = tile * VCOLS + tid * 16;
    const unsigned char* Qp = d_Q + (size_t)i0 * Nn + j;
    const __half2 qa2 = __float2half2_rn(-qafr);
    const __half2 c128 = __float2half2_rn(128.0f);

    float2 fs[8] = {};
    float2 ts[8] = {};

    #pragma unroll
    for (int blk = 0; blk < VROWS / 8; ++blk) {
        unsigned hacc[8] = {};
        #pragma unroll
        for (int it = 0; it < 8; ++it) {
            int i = blk * 8 + it;
            __half2 uc = us2[i];
            uint4 raw = *(const uint4*)(Qp + (size_t)i * Nn);
            unsigned w[4] = {raw.x, raw.y, raw.z, raw.w};
            #pragma unroll
            for (int k = 0; k < 4; ++k) {
                __half2 hA = u32_as_h2(__byte_perm(w[k], 0x64646464u, 0x4140));
                __half2 hB = u32_as_h2(__byte_perm(w[k], 0x64646464u, 0x4342));
                __half2 aA = __hadd2(__hfma2(hA, qa2, c128), uc);
                __half2 aB = __hadd2(__hfma2(hB, qa2, c128), uc);
                __half2 eA = h2exp2_fast(aA);
                __half2 eB = h2exp2_fast(aB);
                __half2 sA = __hadd2(u32_as_h2(hacc[2 * k]), eA);
                __half2 sB = __hadd2(u32_as_h2(hacc[2 * k + 1]), eB);
                hacc[2 * k] = *reinterpret_cast<unsigned*>(&sA);
                hacc[2 * k + 1] = *reinterpret_cast<unsigned*>(&sB);
                if (FINAL) {
                    // a' = hf*(-qafr) + c0f  (log2-domain incl BIAS)
                    float2 hfA = __half22float2(hA);
                    float2 hfB = __half22float2(hB);
                    float2 efA = __half22float2(eA);
                    float2 efB = __half22float2(eB);
                    float apAx = fmaf(hfA.x, -qafr, c0f);
                    float apAy = fmaf(hfA.y, -qafr, c0f);
                    float apBx = fmaf(hfB.x, -qafr, c0f);
                    float apBy = fmaf(hfB.y, -qafr, c0f);
                    ts[2 * k].x = fmaf(apAx, efA.x, ts[2 * k].x);
                    ts[2 * k].y = fmaf(apAy, efA.y, ts[2 * k].y);
                    ts[2 * k + 1].x = fmaf(apBx, efB.x, ts[2 * k + 1].x);
                    ts[2 * k + 1].y = fmaf(apBy, efB.y, ts[2 * k + 1].y);
                }
            }
        }
        #pragma unroll
        for (int q = 0; q < 8; ++q) {
            float2 g = __half22float2(u32_as_h2(hacc[q]));
            fs[q].x += g.x; fs[q].y += g.y;
        }
    }
    #pragma unroll
    for (int q = 0; q < 4; ++q)
        *(float4*)&d_spart[chunk][j + q * 4] =
            make_float4(fs[2 * q].x, fs[2 * q].y, fs[2 * q + 1].x, fs[2 * q + 1].y);
    if (FINAL) {
        #pragma unroll
        for (int q = 0; q < 4; ++q)
            *(float4*)&d_Tpart[chunk][j + q * 4] =
                make_float4(ts[2 * q].x, ts[2 * q].y, ts[2 * q + 1].x, ts[2 * q + 1].y);
    }
}

// deterministic fixed-order merge of v partials
__global__ void vfinalize_kernel() {
    int j = blockIdx.x * blockDim.x + threadIdx.x;
    float s = 0.f;
    #pragma unroll
    for (int c = 0; c < NCHUNK; ++c) s += d_spart[c][j];
    float vp = d_v[j];
    float cc = (vp - LOG_AB) * LOG2E - BIAS;
    d_v[j] = vp - cc * LN2 - __logf(s);
}

// r_j = T_j/s_j in C units: ((sum a'e / sum e) - 12) / alpha2
__global__ void rj_kernel() {
    int j = blockIdx.x * blockDim.x + threadIdx.x;
    float s = 0.f, t = 0.f;
    #pragma unroll
    for (int c = 0; c < NCHUNK; ++c) { s += d_spart[c][j]; t += d_Tpart[c][j]; }
    d_rj[j] = (t / s - BIAS) * d_invAlpha;
}

__global__ void result_kernel(float* __restrict__ out) {
    __shared__ float red[256];
    int tid = threadIdx.x;
    float s = 0.f;
    for (int j = tid; j < Nn; j += 256) s += d_rj[j];
    red[tid] = s;
    __syncthreads();
    for (int o = 128; o; o >>= 1) {
        if (tid < o) red[tid] += red[tid + o];
        __syncthreads();
    }
    if (tid == 0) out[0] = red[0] * (1.0f / Nn);
}

// ---------------------------------------------------------------------------
extern "C" void kernel_launch(void* const* d_in, const int* in_sizes, int n_in,
                              void* d_out, int out_size) {
    const float* XP = (const float*)d_in[0];
    const float* XQ = (const float*)d_in[1];
    float* out = (float*)d_out;

    prep_kernel<<<(2 * Nn) / 8, 256>>>(XP, XQ);
    wmma_gemm_kernel<<<dim3(Nn / 64, Nn / 128), 256>>>();
    scale_kernel<<<1, 1>>>();

    for (int t = 0; t < 20; ++t) {
        upass_kernel<<<Nn / 8, 256>>>();
        if (t < 19) {
            vpass_kernel<false><<<dim3(NTILE, NCHUNK), 128>>>();
            vfinalize_kernel<<<Nn / 256, 256>>>();
        } else {
            vpass_kernel<true><<<dim3(NTILE, NCHUNK), 128>>>();
            rj_kernel<<<Nn / 256, 256>>>();
            result_kernel<<<1, 256>>>(out);
        }
    }
}